// round 12
// baseline (speedup 1.0000x reference)
#include <cuda_runtime.h>

// Problem constants
#define BB   256
#define LL   2048
#define DD   128
#define VV   6000
#define TMAX 48

#define LH       1024              // tokens per CTA (half a batch row)
#define NT       384               // threads per CTA
#define NW       12                // warps per CTA
#define NCTA     (BB * 2)          // 512 CTAs
#define SORT_CAP (LH + TMAX * 8)   // bins padded to x8

// Pre-scaled fp32 table: g_scaled[v][d] = exp(embW[v]) * embX[v][d]. 3MB.
__device__ float g_scaled[(size_t)VV * DD];
// Per-CTA partial sums [512][48][128] (12.6MB) + counts [512][48].
__device__ float g_part[(size_t)NCTA * TMAX * DD];
__device__ float g_pcnt[NCTA * TMAX];

// Kernel 0: build scaled table. One thread per 4 float4s (MLP 5).
__global__ void scale_kernel(const float* __restrict__ embX,
                             const float* __restrict__ embW) {
    int u = blockIdx.x * blockDim.x + threadIdx.x;      // 16-float unit
    if (u < VV * (DD / 16)) {
        int v = u >> 3;                                  // 8 units per row
        const float4* src = reinterpret_cast<const float4*>(embX) + u * 4;
        float4* dst = reinterpret_cast<float4*>(g_scaled) + u * 4;
        float w = embW[v];                               // independent load
        float4 e0 = src[0];
        float4 e1 = src[1];
        float4 e2 = src[2];
        float4 e3 = src[3];
        w = __expf(w);
        dst[0] = make_float4(e0.x * w, e0.y * w, e0.z * w, e0.w * w);
        dst[1] = make_float4(e1.x * w, e1.y * w, e1.z * w, e1.w * w);
        dst[2] = make_float4(e2.x * w, e2.y * w, e2.z * w, e2.w * w);
        dst[3] = make_float4(e3.x * w, e3.y * w, e3.z * w, e3.w * w);
    }
}

// Kernel 1: one CTA per half batch row. Atomic-free counting sort of 1024
// tokens into 48 bins, then rank-balanced warp-per-bin (4 bins/warp) fp32
// register accumulation with 8-deep LDG pipelining; coalesced partial writes.
__global__ void __launch_bounds__(NT, 3)
partial_kernel(const float* __restrict__ X) {
    const int cta  = blockIdx.x;
    const int b    = cta >> 1;
    const int h    = cta & 1;
    const int tid  = threadIdx.x;
    const int warp = tid >> 5;
    const int lane = tid & 31;

    __shared__ __align__(16) int s_sorted[SORT_CAP];
    __shared__ int s_meta[LH];                  // packed (bin<<13)|id
    __shared__ int s_whist[NW * TMAX];
    __shared__ int s_wcur[NW * TMAX];
    __shared__ int s_hist[TMAX];
    __shared__ int s_offP[TMAX + 1];
    __shared__ int s_assign[TMAX];              // (warp,slot) -> bin

    #pragma unroll 1
    for (int i = tid; i < SORT_CAP; i += NT) s_sorted[i] = 0;
    #pragma unroll 1
    for (int i = tid; i < NW * TMAX; i += NT) s_whist[i] = 0;
    __syncthreads();

    // ---------- Phase 0a: meta load + warp-private histogram ----------
    // Trip counts are warp-uniform (boundary 1024 % 384 = 256 is warp-aligned).
    const float2* __restrict__ Xb =
        reinterpret_cast<const float2*>(X) + (size_t)b * LL + h * LH;
    #pragma unroll 1
    for (int t = tid; t < LH; t += NT) {
        float2 m = Xb[t];                       // m.x = T (>=0), m.y = id
        int bin = (int)m.x;                     // trunc == floor for T >= 0
        bin = min(max(bin, 0), TMAX - 1);
        int id = (int)m.y;                      // 1..5999 exact in fp32
        s_meta[t] = (bin << 13) | id;
        unsigned g = __match_any_sync(0xffffffffu, bin);
        if ((int)(__ffs(g) - 1) == lane)        // leader: plain RMW, race-free
            s_whist[warp * TMAX + bin] += __popc(g);
    }
    __syncthreads();

    // ---------- Phase 0b: totals ----------
    if (tid < TMAX) {
        int c = 0;
        #pragma unroll
        for (int w = 0; w < NW; w++) c += s_whist[w * TMAX + tid];
        s_hist[tid] = c;
    }
    __syncthreads();

    // Rank bins by count, snake-partition into 12 warps x 4 slots.
    if (tid < TMAX) {
        int c = s_hist[tid];
        int r = 0;
        #pragma unroll 8
        for (int j = 0; j < TMAX; j++) {
            int cj = s_hist[j];
            r += (cj > c) || (cj == c && j < tid);
        }
        int s = r / NW, i = r - s * NW;
        int w = (s & 1) ? (NW - 1 - i) : i;
        s_assign[w * 4 + s] = tid;
    }
    // Padded (x8) exclusive prefix (pad ids = 0 == zero row).
    if (tid == 0) {
        int acc = 0;
        #pragma unroll
        for (int i = 0; i < TMAX; i++) {
            s_offP[i] = acc;
            acc += (s_hist[i] + 7) & ~7;
        }
        s_offP[TMAX] = acc;
    }
    __syncthreads();

    // Per-(warp,bin) scatter cursors.
    #pragma unroll 1
    for (int i = tid; i < NW * TMAX; i += NT) {
        int w = i / TMAX, bin = i - w * TMAX;
        int c = s_offP[bin];
        for (int w2 = 0; w2 < w; w2++) c += s_whist[w2 * TMAX + bin];
        s_wcur[i] = c;
    }
    __syncthreads();

    // ---------- Phase 0c: atomic-free scatter (same order as 0a) ----------
    #pragma unroll 1
    for (int t = tid; t < LH; t += NT) {
        int m = s_meta[t];
        int bin = m >> 13;
        unsigned g = __match_any_sync(0xffffffffu, bin);
        int leader = __ffs(g) - 1;
        int rank = __popc(g & ((1u << lane) - 1u));
        int base = 0;
        if (lane == leader) {
            base = s_wcur[warp * TMAX + bin];
            s_wcur[warp * TMAX + bin] = base + __popc(g);
        }
        base = __shfl_sync(0xffffffffu, base, leader);
        s_sorted[base + rank] = m & 8191;
    }
    __syncthreads();

    // ---------- Phase 1: warp-per-bin gather, 8-deep LDG pipeline ----------
    const float4* __restrict__ tab = reinterpret_cast<const float4*>(g_scaled);
    float4* __restrict__ part4 = reinterpret_cast<float4*>(g_part);
    #pragma unroll 1
    for (int slot = 0; slot < 4; ++slot) {
        const int bin = s_assign[warp * 4 + slot];
        const int beg = s_offP[bin];
        const int end = s_offP[bin + 1];        // (end-beg) % 8 == 0
        const int cnt = s_hist[bin];

        float ax = 0.f, ay = 0.f, az = 0.f, aw = 0.f;

        #pragma unroll 1
        for (int i = beg; i < end; i += 8) {
            int4 ia = *reinterpret_cast<const int4*>(s_sorted + i);
            int4 ib = *reinterpret_cast<const int4*>(s_sorted + i + 4);
            // 8 independent LDG.128s issued before any consumer.
            float4 e0 = tab[ia.x * 32 + lane];
            float4 e1 = tab[ia.y * 32 + lane];
            float4 e2 = tab[ia.z * 32 + lane];
            float4 e3 = tab[ia.w * 32 + lane];
            float4 e4 = tab[ib.x * 32 + lane];
            float4 e5 = tab[ib.y * 32 + lane];
            float4 e6 = tab[ib.z * 32 + lane];
            float4 e7 = tab[ib.w * 32 + lane];
            ax += ((e0.x + e1.x) + (e2.x + e3.x)) + ((e4.x + e5.x) + (e6.x + e7.x));
            ay += ((e0.y + e1.y) + (e2.y + e3.y)) + ((e4.y + e5.y) + (e6.y + e7.y));
            az += ((e0.z + e1.z) + (e2.z + e3.z)) + ((e4.z + e5.z) + (e6.z + e7.z));
            aw += ((e0.w + e1.w) + (e2.w + e3.w)) + ((e4.w + e5.w) + (e6.w + e7.w));
        }

        part4[((size_t)cta * TMAX + bin) * 32 + lane] =
            make_float4(ax, ay, az, aw);
        if (lane == 0) g_pcnt[cta * TMAX + bin] = (float)cnt;
    }
}

// Kernel 2: merge the two half-row partials and normalize. Two outputs/thread.
__global__ void merge_kernel(float* __restrict__ out) {
    int base = (blockIdx.x * blockDim.x + threadIdx.x) * 2;  // float4 index
    const float4* gp = reinterpret_cast<const float4*>(g_part);
    #pragma unroll
    for (int k = 0; k < 2; k++) {
        int idx = base + k;
        if (idx < BB * TMAX * (DD / 4)) {
            int l   = idx & 31;
            int row = idx >> 5;                 // b*TMAX + bin
            int b   = row / TMAX;
            int bin = row - b * TMAX;
            float4 p0 = gp[((size_t)(2 * b)     * TMAX + bin) * 32 + l];
            float4 p1 = gp[((size_t)(2 * b + 1) * TMAX + bin) * 32 + l];
            float c = g_pcnt[(2 * b) * TMAX + bin] +
                      g_pcnt[(2 * b + 1) * TMAX + bin];
            float inv = 1.0f / (c + 1e-6f);
            reinterpret_cast<float4*>(out)[idx] =
                make_float4((p0.x + p1.x) * inv, (p0.y + p1.y) * inv,
                            (p0.z + p1.z) * inv, (p0.w + p1.w) * inv);
        }
    }
}

extern "C" void kernel_launch(void* const* d_in, const int* in_sizes, int n_in,
                              void* d_out, int out_size) {
    const float* X    = (const float*)d_in[0];   // [B, L, 2] fp32
    const float* embX = (const float*)d_in[1];   // [V, D] fp32
    const float* embW = (const float*)d_in[2];   // [V+1, 1] fp32
    float* out = (float*)d_out;                  // [B, TMAX, D] fp32

    const int SCALE_BLOCKS = (VV * (DD / 16) + 255) / 256;       // 188
    const int MERGE_ELEMS  = BB * TMAX * (DD / 4);               // 393216 float4
    const int MERGE_BLOCKS = (MERGE_ELEMS / 2 + 255) / 256;      // 768

    scale_kernel<<<SCALE_BLOCKS, 256>>>(embX, embW);
    partial_kernel<<<NCTA, NT>>>(X);
    merge_kernel<<<MERGE_BLOCKS, 256>>>(out);
}

// round 14
// speedup vs baseline: 1.5734x; 1.5734x over previous
#include <cuda_runtime.h>

// Problem constants
#define BB   256
#define LL   2048
#define DD   128
#define VV   6000
#define TMAX 48

#define NTHREADS 512
#define NWARPS   16
#define SORT_CAP (LL + 192)        // bins padded to x4 (max 3 pad each)

// Single monolithic kernel: one CTA per batch row.
//   init   : per-CTA smem wtab[v] = exp(embW[v])  (24KB, broadcast-read later)
//   Phase 0: atomic-free counting sort; per-token sorted index computed during
//            the histogram pass (leader RMW + shfl), so the scatter pass is
//            just 2 LDS + 1 STS per token.
//   Phase 1: rank-balanced warp-per-bin FFMA accumulation, direct output.
__global__ void __launch_bounds__(NTHREADS, 2)
embedder_kernel(const float* __restrict__ X,
                const float* __restrict__ embX,
                const float* __restrict__ embW,
                float* __restrict__ out) {
    const int b    = blockIdx.x;
    const int tid  = threadIdx.x;
    const int warp = tid >> 5;
    const int lane = tid & 31;
    const int wrow = warp * TMAX;                       // hoisted

    __shared__ float s_wtab[VV + 4];                    // exp(embW[v]), 24KB
    __shared__ __align__(16) int s_sorted[SORT_CAP];    // bin-sorted ids (pad=0)
    __shared__ int s_meta[LL];          // id:13 | bin:6 | idx-in-(warp,bin):7
    __shared__ int s_whist[NWARPS * TMAX];  // counts, then in-place cursors
    __shared__ int s_hist[TMAX];
    __shared__ int s_offP[TMAX + 1];
    __shared__ int s_assign[TMAX];          // (warp,slot) -> bin

    // ---------- init: wtab + zeroing ----------
    #pragma unroll 2
    for (int i = tid; i < VV + 1; i += NTHREADS)
        s_wtab[i] = __expf(embW[i]);
    #pragma unroll 1
    for (int i = tid; i < SORT_CAP; i += NTHREADS) s_sorted[i] = 0;
    #pragma unroll 1
    for (int i = tid; i < NWARPS * TMAX; i += NTHREADS) s_whist[i] = 0;
    __syncthreads();

    // ---------- Phase 0a: meta + histogram + per-token sorted index ----------
    const float2* __restrict__ Xb =
        reinterpret_cast<const float2*>(X) + (size_t)b * LL;
    #pragma unroll
    for (int it = 0; it < LL / NTHREADS; ++it) {        // 4 iters, warp-uniform
        int t = it * NTHREADS + tid;
        float2 m = Xb[t];                    // m.x = T (>=0), m.y = id
        int bin = (int)m.x;                  // trunc == floor for T >= 0
        bin = min(max(bin, 0), TMAX - 1);
        int id = (int)m.y;                   // 1..5999 exact in fp32
        unsigned g = __match_any_sync(0xffffffffu, bin);
        int leader = __ffs(g) - 1;
        int rank = __popc(g & ((1u << lane) - 1u));
        int old = 0;
        if (lane == leader) {                // leader: plain RMW, race-free
            old = s_whist[wrow + bin];
            s_whist[wrow + bin] = old + __popc(g);
        }
        old = __shfl_sync(0xffffffffu, old, leader);
        // idx within (warp,bin) <= 127 -> fits 7 bits
        s_meta[t] = id | (bin << 13) | ((old + rank) << 19);
    }
    __syncthreads();

    // ---------- Phase 0b: totals ----------
    if (tid < TMAX) {
        int c = 0;
        #pragma unroll
        for (int w = 0; w < NWARPS; w++) c += s_whist[w * TMAX + tid];
        s_hist[tid] = c;
    }
    __syncthreads();

    // Rank bins by count + snake-partition into 16 warps x 3 slots.
    if (tid < TMAX) {
        int c = s_hist[tid];
        int r = 0;
        #pragma unroll 8
        for (int j = 0; j < TMAX; j++) {
            int cj = s_hist[j];
            r += (cj > c) || (cj == c && j < tid);
        }
        int w, slot;
        if (r < NWARPS)          { w = r;                  slot = 0; }
        else if (r < 2 * NWARPS) { w = 2 * NWARPS - 1 - r; slot = 1; }
        else                     { w = r - 2 * NWARPS;     slot = 2; }
        s_assign[w * 3 + slot] = tid;
    }
    // Padded (x4) exclusive prefix (pad ids = 0 == zero embX row).
    if (tid == 0) {
        int acc = 0;
        #pragma unroll
        for (int i = 0; i < TMAX; i++) {
            s_offP[i] = acc;
            acc += (s_hist[i] + 3) & ~3;
        }
        s_offP[TMAX] = acc;
    }
    __syncthreads();

    // In-place transform: s_whist[w][bin] := cursor base for (warp w, bin).
    if (tid < TMAX) {
        int c = s_offP[tid];
        #pragma unroll
        for (int w = 0; w < NWARPS; w++) {
            int tmp = s_whist[w * TMAX + tid];
            s_whist[w * TMAX + tid] = c;
            c += tmp;
        }
    }
    __syncthreads();

    // ---------- Phase 0c: direct scatter (2 LDS + 1 STS per token) ----------
    #pragma unroll
    for (int it = 0; it < LL / NTHREADS; ++it) {
        int t = it * NTHREADS + tid;
        int m = s_meta[t];
        int bin = (m >> 13) & 63;
        int idx = ((unsigned)m) >> 19;
        s_sorted[s_whist[wrow + bin] + idx] = m & 8191;
    }
    __syncthreads();

    // ---------- Phase 1: warp-per-bin FFMA gather, unroll 4 ----------
    const float4* __restrict__ tab = reinterpret_cast<const float4*>(embX);
    #pragma unroll 1
    for (int slot = 0; slot < 3; ++slot) {
        const int bin = s_assign[warp * 3 + slot];
        const int beg = s_offP[bin];
        const int end = s_offP[bin + 1];        // (end-beg) % 4 == 0
        const int cnt = s_hist[bin];

        float ax = 0.f, ay = 0.f, az = 0.f, aw = 0.f;

        #pragma unroll 1
        for (int i = beg; i < end; i += 4) {
            int4 ids = *reinterpret_cast<const int4*>(s_sorted + i);
            float w0 = s_wtab[ids.x];           // broadcast LDS
            float w1 = s_wtab[ids.y];
            float w2 = s_wtab[ids.z];
            float w3 = s_wtab[ids.w];
            float4 e0 = tab[ids.x * 32 + lane]; // 4 in-flight LDG.128
            float4 e1 = tab[ids.y * 32 + lane];
            float4 e2 = tab[ids.z * 32 + lane];
            float4 e3 = tab[ids.w * 32 + lane];
            ax = fmaf(w0, e0.x, ax); ay = fmaf(w0, e0.y, ay);
            az = fmaf(w0, e0.z, az); aw = fmaf(w0, e0.w, aw);
            ax = fmaf(w1, e1.x, ax); ay = fmaf(w1, e1.y, ay);
            az = fmaf(w1, e1.z, az); aw = fmaf(w1, e1.w, aw);
            ax = fmaf(w2, e2.x, ax); ay = fmaf(w2, e2.y, ay);
            az = fmaf(w2, e2.z, az); aw = fmaf(w2, e2.w, aw);
            ax = fmaf(w3, e3.x, ax); ay = fmaf(w3, e3.y, ay);
            az = fmaf(w3, e3.z, az); aw = fmaf(w3, e3.w, aw);
        }

        const float inv = 1.0f / ((float)cnt + 1e-6f);
        float4 o = make_float4(ax * inv, ay * inv, az * inv, aw * inv);
        reinterpret_cast<float4*>(out + ((size_t)b * TMAX + bin) * DD)[lane] = o;
    }
}

extern "C" void kernel_launch(void* const* d_in, const int* in_sizes, int n_in,
                              void* d_out, int out_size) {
    const float* X    = (const float*)d_in[0];   // [B, L, 2] fp32
    const float* embX = (const float*)d_in[1];   // [V, D] fp32
    const float* embW = (const float*)d_in[2];   // [V+1, 1] fp32
    float* out = (float*)d_out;                  // [B, TMAX, D] fp32

    embedder_kernel<<<BB, NTHREADS>>>(X, embX, embW, out);
}